// round 15
// baseline (speedup 1.0000x reference)
#include <cuda_runtime.h>
#include <cuda_fp16.h>
#include <cstdint>
#include <cstddef>

// Problem constants
#define T_STEPS 512
#define BATCH   128
#define DIN     512
#define HID     512
#define G4      2048   // 4*HID

// ---------------------------------------------------------------------------
// Device-global scratch (allocation-free rule)
// ---------------------------------------------------------------------------
__device__ __half g_xh[(size_t)T_STEPS * BATCH * DIN];    // x as fp16
__device__ __half g_hbuf[2][(size_t)BATCH * HID];         // h as fp16, dbl-buf
__device__ unsigned int g_flag[4][T_STEPS][32];           // barrier flags
__device__ unsigned int g_exit;

// ---------------------------------------------------------------------------
// helpers
// ---------------------------------------------------------------------------
__device__ __forceinline__ void mma_f16(float* d,
    uint32_t a0, uint32_t a1, uint32_t a2, uint32_t a3,
    uint32_t b0, uint32_t b1)
{
    asm volatile(
        "mma.sync.aligned.m16n8k16.row.col.f32.f16.f16.f32 "
        "{%0,%1,%2,%3}, {%4,%5,%6,%7}, {%8,%9}, {%0,%1,%2,%3};\n"
        : "+f"(d[0]), "+f"(d[1]), "+f"(d[2]), "+f"(d[3])
        : "r"(a0), "r"(a1), "r"(a2), "r"(a3), "r"(b0), "r"(b1));
}

__device__ __forceinline__ void ldsm4(uint32_t* r, uint32_t addr) {
    asm volatile(
        "ldmatrix.sync.aligned.m8n8.x4.shared.b16 {%0,%1,%2,%3}, [%4];"
        : "=r"(r[0]), "=r"(r[1]), "=r"(r[2]), "=r"(r[3]) : "r"(addr));
}

__device__ __forceinline__ void cp16(uint32_t dst, const void* src) {
    asm volatile("cp.async.cg.shared.global [%0], [%1], 16;" :: "r"(dst), "l"(src));
}
__device__ __forceinline__ void cp_commit() {
    asm volatile("cp.async.commit_group;");
}
template <int N>
__device__ __forceinline__ void cp_wait() {
    asm volatile("cp.async.wait_group %0;" :: "n"(N));
}

#define BAR_SYNC(id, n) \
    asm volatile("bar.sync %0, %1;" :: "r"(id), "r"(n) : "memory")

__device__ __forceinline__ float fsigmoid(float x) {
    return __fdividef(1.0f, 1.0f + __expf(-x));
}
__device__ __forceinline__ float ftanh(float x) {
    float e = __expf(-2.0f * x);
    return __fdividef(2.0f, 1.0f + e) - 1.0f;
}

// ===========================================================================
// Prologue: fp32 -> fp16 conversion (x only)
// ===========================================================================
__global__ void cvt_f16_kernel(const float* __restrict__ src,
                               __half* __restrict__ dst, size_t n4)
{
    size_t i = (size_t)blockIdx.x * blockDim.x + threadIdx.x;
    size_t stride = (size_t)gridDim.x * blockDim.x;
    for (; i < n4; i += stride) {
        float4 v = ((const float4*)src)[i];
        __half2 lo = __floats2half2_rn(v.x, v.y);
        __half2 hi = __floats2half2_rn(v.z, v.w);
        uint2 u;
        u.x = *(uint32_t*)&lo;
        u.y = *(uint32_t*)&hi;
        ((uint2*)dst)[i] = u;
    }
}

// ===========================================================================
// Fused persistent LSTM, 128 blocks x 96 threads:
//   warps 0-1 compute (32m x 32n gate-interleaved each: warp w owns B rows
//   [32w,32w+32) = 8 h-cols), warp 2 loader (flag-poll + h + x staging).
//   Crossbar traffic per GEMM: 2x(32+32)x512x2B = 128KB (was 192KB with
//   4x(32+16)). Input-projection GEMM fused post-release (hides loader).
// ===========================================================================
#define PB_PITCH 1040                               // 512 halves + 16B pad
#define WHS_OFF  0u
#define WXS_OFF  (64u * PB_PITCH)                   // 66560
#define HS_OFF   (WXS_OFF + 64u * PB_PITCH)         // 133120
#define XH_OFF   (HS_OFF + 32u * PB_PITCH)          // 166400
#define SMEM_B_BYTES (XH_OFF + 32u * PB_PITCH + 64) // 199744

#define NTHREADS 96

__global__ __launch_bounds__(NTHREADS, 1) void lstm_rec_kernel(
    const float* __restrict__ Wh,
    const float* __restrict__ Wx,
    const float* __restrict__ bxp,
    const float* __restrict__ bhp,
    float* __restrict__ out)
{
    extern __shared__ uint8_t smB[];
    const uint32_t sb = (uint32_t)__cvta_generic_to_shared(smB);

    const int tid  = threadIdx.x;
    const int warp = tid >> 5;
    const int lane = tid & 31;
    const int g    = lane >> 2;
    const int t    = lane & 3;
    const int odd  = t & 1;

    const int bi = blockIdx.x >> 5;
    const int bj = blockIdx.x & 31;
    const int b0 = bi * 32;
    const int j0 = bj * 16;

    const bool is_loader = (warp == 2);

    // ---- one-time: Wh and Wx slices -> SMEM fp16, gate-interleaved rows ----
    // SMEM row n: w = n>>5, p = n&31 -> gate = p&3, h-col = j0 + w*8 + (p>>2)
    for (int idx = tid; idx < 64 * 512; idx += NTHREADS) {
        int n = idx >> 9;
        int k = idx & 511;
        int w = n >> 5, p = n & 31;
        int grow = (p & 3) * HID + j0 + w * 8 + (p >> 2);
        *(__half*)(smB + WHS_OFF + (uint32_t)n * PB_PITCH + (uint32_t)k * 2) =
            __float2half_rn(Wh[(size_t)grow * HID + k]);
        *(__half*)(smB + WXS_OFF + (uint32_t)n * PB_PITCH + (uint32_t)k * 2) =
            __float2half_rn(Wx[(size_t)grow * DIN + k]);
    }

    // ---- bias registers (compute warps only): bias[nt][gate] ----
    float bias[4][4];
    if (!is_loader) {
#pragma unroll
        for (int nt = 0; nt < 4; nt++) {
            int jc = j0 + warp * 8 + nt * 2 + (t >> 1);
#pragma unroll
            for (int gate = 0; gate < 4; gate++)
                bias[nt][gate] = bxp[gate * HID + jc] + bhp[gate * HID + jc];
        }
    }

    // ---- ldmatrix bases (compute warps) ----
    uint32_t rowsel = (uint32_t)((lane & 15) * PB_PITCH + (lane >> 4) * 16);
    uint32_t aH0 = sb + HS_OFF + rowsel;
    uint32_t aH1 = sb + HS_OFF + (uint32_t)(16 * PB_PITCH) + rowsel;
    uint32_t aX0 = sb + XH_OFF + rowsel;
    uint32_t aX1 = sb + XH_OFF + (uint32_t)(16 * PB_PITCH) + rowsel;
    // B rows: warp's 32 rows split into two 16-row ldsm groups
    uint32_t brow = (uint32_t)((warp * 32 + (lane & 7) + ((lane >> 4) << 3)) * PB_PITCH
                               + ((lane >> 3) & 1) * 16);
    uint32_t aBh0 = sb + WHS_OFF + brow;
    uint32_t aBh1 = aBh0 + (uint32_t)(16 * PB_PITCH);
    uint32_t aBx0 = sb + WXS_OFF + brow;
    uint32_t aBx1 = aBx0 + (uint32_t)(16 * PB_PITCH);

    // ---- loader lambdas (warp 2; 64 chunks of 16B per lane) ----
    auto load_x = [&](int tsn) {
        const __half* src = g_xh + ((size_t)tsn * BATCH + b0) * DIN;
#pragma unroll
        for (int i = 0; i < 64; i++) {
            int id = i * 32 + lane;
            int r  = id >> 6;
            int u  = id & 63;
            cp16(sb + XH_OFF + (uint32_t)(r * PB_PITCH + u * 16),
                 src + (size_t)r * DIN + u * 8);
        }
        cp_commit();
    };
    auto load_h = [&](int tsp) {
        const __half* src = g_hbuf[tsp & 1] + (size_t)b0 * HID;
#pragma unroll
        for (int i = 0; i < 64; i++) {
            int id = i * 32 + lane;
            int r  = id >> 6;
            int u  = id & 63;
            cp16(sb + HS_OFF + (uint32_t)(r * PB_PITCH + u * 16),
                 src + (size_t)r * HID + u * 8);
        }
        cp_commit();
    };

    float accx[2][4][4];
    float accr[2][4][4];
    float cst[2][4];
#pragma unroll
    for (int mt = 0; mt < 2; mt++)
#pragma unroll
        for (int nt = 0; nt < 4; nt++) cst[mt][nt] = 0.0f;

    // GEMM core: acc += A(32x512) @ B(32x512)^T  (B rows = this warp's 32)
    auto gemm32 = [&](uint32_t A0, uint32_t A1, uint32_t B0, uint32_t B1,
                      float (*acc)[4][4]) {
#pragma unroll 4
        for (int s = 0; s < 32; s++) {
            uint32_t ko = (uint32_t)(s * 32);
            uint32_t a0[4], a1[4], b0[4], b1[4];
            ldsm4(a0, A0 + ko);
            ldsm4(a1, A1 + ko);
            ldsm4(b0, B0 + ko);
            ldsm4(b1, B1 + ko);
            mma_f16(acc[0][0], a0[0], a0[1], a0[2], a0[3], b0[0], b0[1]);
            mma_f16(acc[0][1], a0[0], a0[1], a0[2], a0[3], b0[2], b0[3]);
            mma_f16(acc[0][2], a0[0], a0[1], a0[2], a0[3], b1[0], b1[1]);
            mma_f16(acc[0][3], a0[0], a0[1], a0[2], a0[3], b1[2], b1[3]);
            mma_f16(acc[1][0], a1[0], a1[1], a1[2], a1[3], b0[0], b0[1]);
            mma_f16(acc[1][1], a1[0], a1[1], a1[2], a1[3], b0[2], b0[3]);
            mma_f16(acc[1][2], a1[0], a1[1], a1[2], a1[3], b1[0], b1[1]);
            mma_f16(acc[1][3], a1[0], a1[1], a1[2], a1[3], b1[2], b1[3]);
        }
    };

    auto xg_gemm = [&]() {
#pragma unroll
        for (int mt = 0; mt < 2; mt++)
#pragma unroll
            for (int nt = 0; nt < 4; nt++)
#pragma unroll
                for (int q = 0; q < 4; q++) accx[mt][nt][q] = 0.0f;
        gemm32(aX0, aX1, aBx0, aBx1, accx);
    };

    // ---- prologue: x[0] -> Xh (loader), xg-gemm for ts=0 (compute) ----
    if (is_loader) { load_x(0); cp_wait<0>(); }
    __syncthreads();        // weights + x[0] visible to all
    if (!is_loader) xg_gemm();

    for (int ts = 0; ts < T_STEPS; ts++) {
        if (is_loader) {
            if (ts > 0) {
                const unsigned int* fp = &g_flag[bi][ts - 1][lane];
                unsigned v;
                do {
                    asm volatile("ld.acquire.gpu.global.u32 %0, [%1];"
                                 : "=r"(v) : "l"(fp) : "memory");
                } while (!v);
                __syncwarp();
                load_h(ts - 1);
                cp_wait<0>();
            }
            BAR_SYNC(1, NTHREADS);             // barA: h ready / Xh consumed
            if (ts + 1 < T_STEPS) {
                load_x(ts + 1);
                cp_wait<0>();
                BAR_SYNC(3, NTHREADS);         // barB: x[ts+1] ready
            }
        } else {
            // ---- compute ----
#pragma unroll
            for (int mt = 0; mt < 2; mt++)
#pragma unroll
                for (int nt = 0; nt < 4; nt++)
#pragma unroll
                    for (int q = 0; q < 4; q++) accr[mt][nt][q] = accx[mt][nt][q];

            BAR_SYNC(1, NTHREADS);             // barA

            if (ts > 0) {
                gemm32(aH0, aH1, aBh0, aBh1, accr);    // recurrent GEMM
            }

            // ---- warp-local elementwise (gate shuffle), 8 elems/thread ----
            float hout[2][4];
#pragma unroll
            for (int mt = 0; mt < 2; mt++) {
#pragma unroll
                for (int nt = 0; nt < 4; nt++) {
                    float q0 = accr[mt][nt][0], q1 = accr[mt][nt][1];
                    float q2 = accr[mt][nt][2], q3 = accr[mt][nt][3];
                    float sx = odd ? q0 : q2;
                    float sy = odd ? q1 : q3;
                    float rx = __shfl_xor_sync(0xffffffffu, sx, 1);
                    float ry = __shfl_xor_sync(0xffffffffu, sy, 1);
                    float gi = (odd ? rx : q0) + bias[nt][0];
                    float gf = (odd ? ry : q1) + bias[nt][1];
                    float gg = (odd ? q2 : rx) + bias[nt][2];
                    float go = (odd ? q3 : ry) + bias[nt][3];

                    float iv = fsigmoid(gi), fv = fsigmoid(gf);
                    float gv = ftanh(gg),    ov = fsigmoid(go);
                    float cn = cst[mt][nt] * fv + iv * gv;
                    cst[mt][nt] = cn;
                    float h = ov * ftanh(cn);
                    hout[mt][nt] = h;

                    int rl = mt * 16 + g + (odd << 3);
                    int jl = warp * 8 + nt * 2 + (t >> 1);
                    g_hbuf[ts & 1][(size_t)(b0 + rl) * HID + j0 + jl] =
                        __float2half_rn(h);
                }
            }

            BAR_SYNC(2, 64);                   // compute-only: stores ordered

            if (ts < T_STEPS - 1 && tid == 0) {
                asm volatile("st.release.gpu.global.u32 [%0], %1;"
                             :: "l"(&g_flag[bi][ts][bj]), "r"(1u) : "memory");
            }

            // out fp32 stores (off the inter-block critical path)
            {
                float* obase = out + (size_t)ts * (BATCH * HID);
#pragma unroll
                for (int mt = 0; mt < 2; mt++)
#pragma unroll
                    for (int nt = 0; nt < 4; nt++) {
                        int rl = mt * 16 + g + (odd << 3);
                        int jl = warp * 8 + nt * 2 + (t >> 1);
                        obase[(size_t)(b0 + rl) * HID + j0 + jl] = hout[mt][nt];
                    }
            }

            if (ts + 1 < T_STEPS) {
                BAR_SYNC(3, NTHREADS);         // barB: x[ts+1] in Xh
                xg_gemm();                     // hides loader's poll + h load
            }
        }
    }

    // ---- exit: last block resets barrier state for next graph replay ----
    __syncthreads();
    volatile unsigned* rflag = (volatile unsigned*)(smB + XH_OFF);
    if (tid == 0) {
        unsigned old;
        asm volatile("atom.acq_rel.gpu.add.u32 %0, [%1], 1;"
                     : "=r"(old) : "l"(&g_exit) : "memory");
        *rflag = (old == 127u) ? 1u : 0u;
    }
    __syncthreads();
    if (*rflag != 0u) {
        unsigned int* fl = &g_flag[0][0][0];
        for (int i = tid; i < 4 * T_STEPS * 32; i += NTHREADS) fl[i] = 0u;
        __threadfence();
        if (tid == 0) g_exit = 0u;
    }
}

// ===========================================================================
// Launch
// ===========================================================================
extern "C" void kernel_launch(void* const* d_in, const int* in_sizes, int n_in,
                              void* d_out, int out_size)
{
    (void)in_sizes; (void)n_in; (void)out_size;
    const float* x  = (const float*)d_in[0];
    const float* Wx = (const float*)d_in[1];
    const float* bx = (const float*)d_in[2];
    const float* Wh = (const float*)d_in[3];
    const float* bh = (const float*)d_in[4];
    float* out = (float*)d_out;

    __half* xh;  cudaGetSymbolAddress((void**)&xh,  g_xh);

    cudaFuncSetAttribute(lstm_rec_kernel,
                         cudaFuncAttributeMaxDynamicSharedMemorySize, SMEM_B_BYTES);

    // x: fp32 -> fp16
    cvt_f16_kernel<<<2048, 256>>>(x, xh, (size_t)T_STEPS * BATCH * DIN / 4);

    // fused persistent LSTM
    lstm_rec_kernel<<<128, NTHREADS, SMEM_B_BYTES>>>(Wh, Wx, bx, bh, out);
}

// round 16
// speedup vs baseline: 1.0828x; 1.0828x over previous
#include <cuda_runtime.h>
#include <cuda_fp16.h>
#include <cstdint>
#include <cstddef>

// Problem constants
#define T_STEPS 512
#define BATCH   128
#define DIN     512
#define HID     512
#define G4      2048   // 4*HID

// ---------------------------------------------------------------------------
// Device-global scratch (allocation-free rule)
// g_hbuf layout is BLOCK-CHUNKED: [parity][bi][bj][32 rows][16 cols] fp16.
// Each block publishes ONE contiguous 1KB chunk per step (8 L2 lines), so the
// st.release drain and the peers' gather are line-local instead of scattered.
// ---------------------------------------------------------------------------
__device__ __half g_xh[(size_t)T_STEPS * BATCH * DIN];    // x as fp16
__device__ __half g_hbuf[2][4][32][32][16];               // chunked h exchange
__device__ unsigned int g_flag[4][T_STEPS][32];           // barrier flags
__device__ unsigned int g_exit;

// ---------------------------------------------------------------------------
// helpers
// ---------------------------------------------------------------------------
__device__ __forceinline__ void mma_f16(float* d,
    uint32_t a0, uint32_t a1, uint32_t a2, uint32_t a3,
    uint32_t b0, uint32_t b1)
{
    asm volatile(
        "mma.sync.aligned.m16n8k16.row.col.f32.f16.f16.f32 "
        "{%0,%1,%2,%3}, {%4,%5,%6,%7}, {%8,%9}, {%0,%1,%2,%3};\n"
        : "+f"(d[0]), "+f"(d[1]), "+f"(d[2]), "+f"(d[3])
        : "r"(a0), "r"(a1), "r"(a2), "r"(a3), "r"(b0), "r"(b1));
}

__device__ __forceinline__ void ldsm4(uint32_t* r, uint32_t addr) {
    asm volatile(
        "ldmatrix.sync.aligned.m8n8.x4.shared.b16 {%0,%1,%2,%3}, [%4];"
        : "=r"(r[0]), "=r"(r[1]), "=r"(r[2]), "=r"(r[3]) : "r"(addr));
}

__device__ __forceinline__ void cp16(uint32_t dst, const void* src) {
    asm volatile("cp.async.cg.shared.global [%0], [%1], 16;" :: "r"(dst), "l"(src));
}
__device__ __forceinline__ void cp_commit() {
    asm volatile("cp.async.commit_group;");
}
template <int N>
__device__ __forceinline__ void cp_wait() {
    asm volatile("cp.async.wait_group %0;" :: "n"(N));
}

#define BAR_SYNC(id, n) \
    asm volatile("bar.sync %0, %1;" :: "r"(id), "r"(n) : "memory")

__device__ __forceinline__ float fsigmoid(float x) {
    return __fdividef(1.0f, 1.0f + __expf(-x));
}
__device__ __forceinline__ float ftanh(float x) {
    float e = __expf(-2.0f * x);
    return __fdividef(2.0f, 1.0f + e) - 1.0f;
}

// ===========================================================================
// Prologue: fp32 -> fp16 conversion (x only)
// ===========================================================================
__global__ void cvt_f16_kernel(const float* __restrict__ src,
                               __half* __restrict__ dst, size_t n4)
{
    size_t i = (size_t)blockIdx.x * blockDim.x + threadIdx.x;
    size_t stride = (size_t)gridDim.x * blockDim.x;
    for (; i < n4; i += stride) {
        float4 v = ((const float4*)src)[i];
        __half2 lo = __floats2half2_rn(v.x, v.y);
        __half2 hi = __floats2half2_rn(v.z, v.w);
        uint2 u;
        u.x = *(uint32_t*)&lo;
        u.y = *(uint32_t*)&hi;
        ((uint2*)dst)[i] = u;
    }
}

// ===========================================================================
// Fused persistent LSTM, 128 blocks x 160 threads (R10 structure, proven):
//   warps 0-3 compute (32m x 16n gate-interleaved), warp 4 loader.
//   Loader hides flag-poll + h cp.async behind the compute warps' fused
//   input-projection GEMM. THIS ROUND: h exchange through block-chunked
//   g_hbuf (contiguous 1KB per block) to cut release-drain + gather latency.
// ===========================================================================
#define PB_PITCH 1040                               // 512 halves + 16B pad
#define WHS_OFF  0u
#define WXS_OFF  (64u * PB_PITCH)                   // 66560
#define HS_OFF   (WXS_OFF + 64u * PB_PITCH)         // 133120
#define XH_OFF   (HS_OFF + 32u * PB_PITCH)          // 166400
#define SMEM_B_BYTES (XH_OFF + 32u * PB_PITCH + 64) // 199744

#define NTHREADS 160

__global__ __launch_bounds__(NTHREADS, 1) void lstm_rec_kernel(
    const float* __restrict__ Wh,
    const float* __restrict__ Wx,
    const float* __restrict__ bxp,
    const float* __restrict__ bhp,
    float* __restrict__ out)
{
    extern __shared__ uint8_t smB[];
    const uint32_t sb = (uint32_t)__cvta_generic_to_shared(smB);

    const int tid  = threadIdx.x;
    const int warp = tid >> 5;
    const int lane = tid & 31;
    const int g    = lane >> 2;
    const int t    = lane & 3;
    const int odd  = t & 1;

    const int bi = blockIdx.x >> 5;
    const int bj = blockIdx.x & 31;
    const int b0 = bi * 32;
    const int j0 = bj * 16;

    const bool is_loader = (warp == 4);

    // ---- one-time: Wh and Wx slices -> SMEM fp16, gate-interleaved rows ----
    for (int idx = tid; idx < 64 * 512; idx += NTHREADS) {
        int n = idx >> 9;
        int k = idx & 511;
        int w = n >> 4, p = n & 15;
        int grow = (p & 3) * HID + j0 + w * 4 + (p >> 2);
        *(__half*)(smB + WHS_OFF + (uint32_t)n * PB_PITCH + (uint32_t)k * 2) =
            __float2half_rn(Wh[(size_t)grow * HID + k]);
        *(__half*)(smB + WXS_OFF + (uint32_t)n * PB_PITCH + (uint32_t)k * 2) =
            __float2half_rn(Wx[(size_t)grow * DIN + k]);
    }

    // ---- bias registers (compute warps only) ----
    float bias[2][4];
    if (!is_loader) {
#pragma unroll
        for (int nt = 0; nt < 2; nt++) {
            int jc = j0 + warp * 4 + (t >> 1) + 2 * nt;
#pragma unroll
            for (int gate = 0; gate < 4; gate++)
                bias[nt][gate] = bxp[gate * HID + jc] + bhp[gate * HID + jc];
        }
    }

    // ---- ldmatrix bases (compute warps; R8 mapping) ----
    uint32_t rowsel = (uint32_t)((lane & 15) * PB_PITCH + (lane >> 4) * 16);
    uint32_t aH0 = sb + HS_OFF + rowsel;
    uint32_t aH1 = sb + HS_OFF + (uint32_t)(16 * PB_PITCH) + rowsel;
    uint32_t aX0 = sb + XH_OFF + rowsel;
    uint32_t aX1 = sb + XH_OFF + (uint32_t)(16 * PB_PITCH) + rowsel;
    uint32_t brow = (uint32_t)(((warp & 3) * 16 + (lane & 7) + ((lane >> 4) << 3)) * PB_PITCH
                               + ((lane >> 3) & 1) * 16);
    uint32_t aBh = sb + WHS_OFF + brow;
    uint32_t aBx = sb + WXS_OFF + brow;

    // ---- loader lambdas (warp 4; 64 chunks of 16B per lane) ----
    auto load_x = [&](int tsn) {
        const __half* src = g_xh + ((size_t)tsn * BATCH + b0) * DIN;
#pragma unroll
        for (int i = 0; i < 64; i++) {
            int id = i * 32 + lane;
            int r  = id >> 6;
            int u  = id & 63;
            cp16(sb + XH_OFF + (uint32_t)(r * PB_PITCH + u * 16),
                 src + (size_t)r * DIN + u * 8);
        }
        cp_commit();
    };
    // gather h from the 32 chunked peer regions of this bi-group
    auto load_h = [&](int tsp) {
        const __half* base = &g_hbuf[tsp & 1][bi][0][0][0];
#pragma unroll
        for (int i = 0; i < 64; i++) {
            int id = i * 32 + lane;      // 0..2047
            int r  = id >> 6;            // 0..31 (row)
            int u  = id & 63;            // 16B unit within the 1KB row span
            // Hs[r][u*8 .. u*8+7]  <-  chunk bj'=(u>>1), half-row (u&1)
            cp16(sb + HS_OFF + (uint32_t)(r * PB_PITCH + u * 16),
                 base + (size_t)(u >> 1) * 512 + (size_t)r * 16 + (u & 1) * 8);
        }
        cp_commit();
    };

    float accx[2][2][4];
    float accr[2][2][4];
    float cst[2][2] = {{0.f, 0.f}, {0.f, 0.f}};

    auto xg_gemm = [&]() {
#pragma unroll
        for (int mt = 0; mt < 2; mt++)
#pragma unroll
            for (int nt = 0; nt < 2; nt++)
#pragma unroll
                for (int q = 0; q < 4; q++) accx[mt][nt][q] = 0.0f;
#pragma unroll 4
        for (int s = 0; s < 32; s++) {
            uint32_t ko = (uint32_t)(s * 32);
            uint32_t a0[4], a1[4], bb[4];
            ldsm4(a0, aX0 + ko);
            ldsm4(a1, aX1 + ko);
            ldsm4(bb, aBx + ko);
            mma_f16(accx[0][0], a0[0], a0[1], a0[2], a0[3], bb[0], bb[1]);
            mma_f16(accx[0][1], a0[0], a0[1], a0[2], a0[3], bb[2], bb[3]);
            mma_f16(accx[1][0], a1[0], a1[1], a1[2], a1[3], bb[0], bb[1]);
            mma_f16(accx[1][1], a1[0], a1[1], a1[2], a1[3], bb[2], bb[3]);
        }
    };

    // ---- prologue: x[0] -> Xh (loader), xg-gemm for ts=0 (compute) ----
    if (is_loader) { load_x(0); cp_wait<0>(); }
    __syncthreads();        // weights + x[0] visible to all
    if (!is_loader) xg_gemm();

    for (int ts = 0; ts < T_STEPS; ts++) {
        if (is_loader) {
            if (ts > 0) {
                // poll flags (one per lane), then gather h_{ts-1}
                const unsigned int* fp = &g_flag[bi][ts - 1][lane];
                unsigned v;
                do {
                    asm volatile("ld.acquire.gpu.global.u32 %0, [%1];"
                                 : "=r"(v) : "l"(fp) : "memory");
                } while (!v);
                __syncwarp();
                load_h(ts - 1);
                cp_wait<0>();
            }
            BAR_SYNC(1, NTHREADS);             // barA: h ready / Xh consumed
            if (ts + 1 < T_STEPS) {
                load_x(ts + 1);
                cp_wait<0>();
                BAR_SYNC(3, NTHREADS);         // barB: x[ts+1] ready
            }
        } else {
            // ---- compute ----
#pragma unroll
            for (int mt = 0; mt < 2; mt++)
#pragma unroll
                for (int nt = 0; nt < 2; nt++)
#pragma unroll
                    for (int q = 0; q < 4; q++) accr[mt][nt][q] = accx[mt][nt][q];

            BAR_SYNC(1, NTHREADS);             // barA

            if (ts > 0) {
                // recurrent GEMM: Hs @ Whs (accumulate into accr)
#pragma unroll 4
                for (int s = 0; s < 32; s++) {
                    uint32_t ko = (uint32_t)(s * 32);
                    uint32_t a0[4], a1[4], bb[4];
                    ldsm4(a0, aH0 + ko);
                    ldsm4(a1, aH1 + ko);
                    ldsm4(bb, aBh + ko);
                    mma_f16(accr[0][0], a0[0], a0[1], a0[2], a0[3], bb[0], bb[1]);
                    mma_f16(accr[0][1], a0[0], a0[1], a0[2], a0[3], bb[2], bb[3]);
                    mma_f16(accr[1][0], a1[0], a1[1], a1[2], a1[3], bb[0], bb[1]);
                    mma_f16(accr[1][1], a1[0], a1[1], a1[2], a1[3], bb[2], bb[3]);
                }
            }

            // ---- warp-local elementwise (gate shuffle), 4 elems/thread ----
            float hout[2][2];
#pragma unroll
            for (int mt = 0; mt < 2; mt++) {
#pragma unroll
                for (int nt = 0; nt < 2; nt++) {
                    float q0 = accr[mt][nt][0], q1 = accr[mt][nt][1];
                    float q2 = accr[mt][nt][2], q3 = accr[mt][nt][3];
                    float sx = odd ? q0 : q2;
                    float sy = odd ? q1 : q3;
                    float rx = __shfl_xor_sync(0xffffffffu, sx, 1);
                    float ry = __shfl_xor_sync(0xffffffffu, sy, 1);
                    float gi = (odd ? rx : q0) + bias[nt][0];
                    float gf = (odd ? ry : q1) + bias[nt][1];
                    float gg = (odd ? q2 : rx) + bias[nt][2];
                    float go = (odd ? q3 : ry) + bias[nt][3];

                    float iv = fsigmoid(gi), fv = fsigmoid(gf);
                    float gv = ftanh(gg),    ov = fsigmoid(go);
                    float cn = cst[mt][nt] * fv + iv * gv;
                    cst[mt][nt] = cn;
                    float h = ov * ftanh(cn);
                    hout[mt][nt] = h;

                    // chunked publish: contiguous 1KB region per block
                    int rl = mt * 16 + g + (odd << 3);
                    int jl = (warp & 3) * 4 + (t >> 1) + 2 * nt;
                    g_hbuf[ts & 1][bi][bj][rl][jl] = __float2half_rn(h);
                }
            }

            BAR_SYNC(2, 128);                  // compute-only: stores ordered

            if (ts < T_STEPS - 1 && tid == 0) {
                asm volatile("st.release.gpu.global.u32 [%0], %1;"
                             :: "l"(&g_flag[bi][ts][bj]), "r"(1u) : "memory");
            }

            // out fp32 stores (off the inter-block critical path)
            {
                float* obase = out + (size_t)ts * (BATCH * HID);
#pragma unroll
                for (int mt = 0; mt < 2; mt++)
#pragma unroll
                    for (int nt = 0; nt < 2; nt++) {
                        int rl = mt * 16 + g + (odd << 3);
                        int jl = (warp & 3) * 4 + (t >> 1) + 2 * nt;
                        obase[(size_t)(b0 + rl) * HID + j0 + jl] = hout[mt][nt];
                    }
            }

            if (ts + 1 < T_STEPS) {
                BAR_SYNC(3, NTHREADS);         // barB: x[ts+1] in Xh
                xg_gemm();                     // hides loader's poll + h gather
            }
        }
    }

    // ---- exit: last block resets barrier state for next graph replay ----
    __syncthreads();
    volatile unsigned* rflag = (volatile unsigned*)(smB + XH_OFF);
    if (tid == 0) {
        unsigned old;
        asm volatile("atom.acq_rel.gpu.add.u32 %0, [%1], 1;"
                     : "=r"(old) : "l"(&g_exit) : "memory");
        *rflag = (old == 127u) ? 1u : 0u;
    }
    __syncthreads();
    if (*rflag != 0u) {
        unsigned int* fl = &g_flag[0][0][0];
        for (int i = tid; i < 4 * T_STEPS * 32; i += NTHREADS) fl[i] = 0u;
        __threadfence();
        if (tid == 0) g_exit = 0u;
    }
}

// ===========================================================================
// Launch
// ===========================================================================
extern "C" void kernel_launch(void* const* d_in, const int* in_sizes, int n_in,
                              void* d_out, int out_size)
{
    (void)in_sizes; (void)n_in; (void)out_size;
    const float* x  = (const float*)d_in[0];
    const float* Wx = (const float*)d_in[1];
    const float* bx = (const float*)d_in[2];
    const float* Wh = (const float*)d_in[3];
    const float* bh = (const float*)d_in[4];
    float* out = (float*)d_out;

    __half* xh;  cudaGetSymbolAddress((void**)&xh,  g_xh);

    cudaFuncSetAttribute(lstm_rec_kernel,
                         cudaFuncAttributeMaxDynamicSharedMemorySize, SMEM_B_BYTES);

    // x: fp32 -> fp16
    cvt_f16_kernel<<<2048, 256>>>(x, xh, (size_t)T_STEPS * BATCH * DIN / 4);

    // fused persistent LSTM
    lstm_rec_kernel<<<128, NTHREADS, SMEM_B_BYTES>>>(Wh, Wx, bx, bh, out);
}